// round 11
// baseline (speedup 1.0000x reference)
#include <cuda_runtime.h>
#include <math.h>

// ---------------------------------------------------------------------------
// RadiomicsPreservationLoss — interior-specialized shuffle-halo stencil.
// Interior rows (1..510): zero boundary logic — 3 unconditional LDG.128 at
// immediate offsets off a walking pointer, 6 shuffles + single predicated
// edge-lane fixup per image. Image-edge rows take a guarded variant that
// constant-folds from the same inline function. Balanced contiguous row-runs,
// occ-3, 444 blocks, fused last-block finalize.
// inputs: input_img, output_img, roi_mask  [32,1,512,512] f32
// output: [intensity, texture, shape, total] (4 x f32)
// ---------------------------------------------------------------------------

#define HH 512
#define WW 512
#define BB 32
#define NBLK 444                 // 3 blocks/SM
#define NTHR 256
#define NSLOTS (NBLK * 8)        // 3552 warp slots
#define RU 65536                 // 128 stripcols * 512 rows
#define RUQ (RU / NSLOTS)        // 18
#define RUR (RU % NSLOTS)        // 1600
#define FULLM 0xffffffffu

__device__ double g_part[NBLK][11];
__device__ unsigned g_cnt = 0;

// 3x3 variance + laplacian + center for the lane's 4 pixels at pointer p.
// okm/okp are passed as literals at each call site -> constant-folded.
// c0/c31: lane is warp-edge; el: lane needs real halo loads (edge lane with
// in-image halo); eo: halo column offset (-1 left lane, +4 right lane).
__device__ __forceinline__ void sten(
    const float* __restrict__ p, bool okm, bool okp,
    bool c0, bool c31, bool el, int eo,
    float* __restrict__ var, float* __restrict__ lap, float* __restrict__ cen)
{
    const float4 z4 = make_float4(0.f, 0.f, 0.f, 0.f);
    float4 qm = okm ? *(const float4*)(p - WW) : z4;
    float4 qc = *(const float4*)(p);
    float4 qp = okp ? *(const float4*)(p + WW) : z4;

    // predicated halo loads: at most 2 active lanes per warp
    float h0 = 0.f, h1 = 0.f, h2 = 0.f;
    if (el) {
        if (okm) h0 = p[eo - WW];
        h1 = p[eo];
        if (okp) h2 = p[eo + WW];
    }

    float a0[4] = { qm.x, qm.y, qm.z, qm.w };
    float a1[4] = { qc.x, qc.y, qc.z, qc.w };
    float a2[4] = { qp.x, qp.y, qp.z, qp.w };

    float cs[4], cq[4];
    #pragma unroll
    for (int j = 0; j < 4; j++) {
        cs[j] = a0[j] + a1[j] + a2[j];
        float u = a0[j] * a0[j];
        u = fmaf(a1[j], a1[j], u);
        cq[j] = fmaf(a2[j], a2[j], u);
    }
    float hcs = h0 + h1 + h2;
    float hcq = fmaf(h2, h2, fmaf(h1, h1, h0 * h0));

    float csL = __shfl_up_sync(FULLM, cs[3], 1);
    float cqL = __shfl_up_sync(FULLM, cq[3], 1);
    float aL  = __shfl_up_sync(FULLM, a1[3], 1);
    float csR = __shfl_down_sync(FULLM, cs[0], 1);
    float cqR = __shfl_down_sync(FULLM, cq[0], 1);
    float aR  = __shfl_down_sync(FULLM, a1[0], 1);
    csL = c0 ? hcs : csL;  cqL = c0 ? hcq : cqL;  aL = c0 ? h1 : aL;
    csR = c31 ? hcs : csR; cqR = c31 ? hcq : cqR; aR = c31 ? h1 : aR;

    const float inv9 = 1.f / 9.f;
    #pragma unroll
    for (int j = 0; j < 4; j++) {
        float cm = (j == 0) ? csL : cs[j - 1];
        float cp = (j == 3) ? csR : cs[j + 1];
        float qm2 = (j == 0) ? cqL : cq[j - 1];
        float qp2 = (j == 3) ? cqR : cq[j + 1];
        float S = cm + cs[j] + cp;
        float Q = qm2 + cq[j] + qp2;
        float bmn = S * inv9;
        var[j] = fmaf(-bmn, bmn, Q * inv9);
        float am = (j == 0) ? aL : a1[j - 1];
        float ap = (j == 3) ? aR : a1[j + 1];
        lap[j] = fmaf(-5.f, a1[j], cs[j] + am + ap);
        cen[j] = a1[j];
    }
}

__global__ void __launch_bounds__(NTHR, 3) k_main(
    const float* __restrict__ g_in,
    const float* __restrict__ g_out,
    const float* __restrict__ g_mask,
    float* __restrict__ final_out)
{
    __shared__ float sred[11][8];
    __shared__ bool s_last;
    __shared__ double sacc[11];

    const int t    = threadIdx.x;
    const int lane = t & 31;
    const int wid  = t >> 5;
    const int slot = blockIdx.x * 8 + wid;   // 0..3551

    const bool c0  = (lane == 0);
    const bool c31 = (lane == 31);
    const int  eo  = c0 ? -1 : 4;

    float msum = 0.f;
    float xi1 = 0.f, xi2 = 0.f, xi3 = 0.f, xi4 = 0.f;
    float yo1 = 0.f, yo2 = 0.f, yo3 = 0.f, yo4 = 0.f;
    float texs = 0.f, shps = 0.f;

    int u = slot * RUQ + min(slot, RUR);
    const int uend = u + RUQ + (slot < RUR ? 1 : 0);

#define PROC(OKM, OKP)                                                      \
    do {                                                                    \
        float4 m0 = *(const float4*)pm;                                     \
        float vi[4], li[4], xc[4];                                          \
        sten(pi, OKM, OKP, c0, c31, el, eo, vi, li, xc);                    \
        float vo[4], lo[4], yc[4];                                          \
        sten(po, OKM, OKP, c0, c31, el, eo, vo, lo, yc);                    \
        float mv[4] = { m0.x, m0.y, m0.z, m0.w };                           \
        _Pragma("unroll")                                                   \
        for (int j = 0; j < 4; j++) {                                       \
            float m = mv[j];                                                \
            msum += m;                                                      \
            float x = xc[j], y = yc[j];                                     \
            float x2 = x * x, y2 = y * y;                                   \
            float qx = x2 * m, qy = y2 * m;                                 \
            xi1 = fmaf(x, m, xi1);  xi2 += qx;                              \
            xi3 = fmaf(x, qx, xi3); xi4 = fmaf(x2, qx, xi4);                \
            yo1 = fmaf(y, m, yo1);  yo2 += qy;                              \
            yo3 = fmaf(y, qy, yo3); yo4 = fmaf(y2, qy, yo4);                \
            texs = fmaf(fabsf(vo[j] - vi[j]), m, texs);                     \
            shps = fmaf(fabsf(lo[j] - li[j]), m, shps);                     \
        }                                                                   \
        pi += WW; po += WW; pm += WW;                                       \
    } while (0)

    while (u < uend) {
        const int scol  = u >> 9;              // stripcol 0..127
        const int ra    = u & 511;
        const int n     = min(uend - u, HH - ra);
        const int img   = scol >> 2;
        const int strip = scol & 3;
        const int cb    = (strip << 7) + lane * 4;
        // edge-lane fixup needed iff the halo column exists in the image
        const bool el = (c0 && strip > 0) || (c31 && strip < 3);

        const size_t base = (size_t)img * (HH * WW) + (size_t)ra * WW + cb;
        const float* pi = g_in   + base;
        const float* po = g_out  + base;
        const float* pm = g_mask + base;

        int r = ra;
        const int rend = ra + n;

        if (r == 0) { PROC(false, true); r++; }          // top image edge
        const int rstop = min(rend, HH - 1);             // interior: r <= 510
        for (; r < rstop; r++) { PROC(true, true); }     // guard-free hot loop
        if (r < rend) { PROC(true, false); r++; }        // bottom image edge

        u += n;
    }
#undef PROC

    // ---- block reduction -> fp64 partial ----
    float acc[11] = { msum, xi1, xi2, xi3, xi4, yo1, yo2, yo3, yo4, texs, shps };
    #pragma unroll
    for (int k = 0; k < 11; k++) {
        float v = acc[k];
        #pragma unroll
        for (int off = 16; off; off >>= 1)
            v += __shfl_xor_sync(FULLM, v, off);
        if (lane == 0) sred[k][wid] = v;
    }
    __syncthreads();
    if (t < 11) {
        double s = 0.0;
        #pragma unroll
        for (int w = 0; w < 8; w++) s += (double)sred[t][w];
        g_part[blockIdx.x][t] = s;
    }

    // ---- last-block finalize ----
    __threadfence();
    if (t == 0) {
        unsigned prev = atomicAdd(&g_cnt, 1u);
        s_last = (prev == NBLK - 1);
    }
    __syncthreads();
    if (!s_last) return;

    for (int k = wid; k < 11; k += 8) {
        double s = 0.0;
        for (int b = lane; b < NBLK; b += 32)
            s += g_part[b][k];
        #pragma unroll
        for (int off = 16; off; off >>= 1)
            s += __shfl_xor_sync(FULLM, s, off);
        if (lane == 0) sacc[k] = s;
    }
    __syncthreads();

    if (t == 0) {
        g_cnt = 0;   // reset for next graph replay
        const double EPS = 1e-8;
        const double NTOT = (double)BB * HH * WW;

        double M0 = sacc[0];
        double ms = M0 + EPS;
        double Mi1 = sacc[1], Mi2 = sacc[2], Mi3 = sacc[3], Mi4 = sacc[4];
        double Mo1 = sacc[5], Mo2 = sacc[6], Mo3 = sacc[7], Mo4 = sacc[8];

        double im = Mi1 / ms, om = Mo1 / ms;
        double im2 = im * im, om2 = om * om;

        double c2i = Mi2 - 2.0 * im * Mi1 + im2 * M0;
        double c3i = Mi3 - 3.0 * im * Mi2 + 3.0 * im2 * Mi1 - im2 * im * M0;
        double c4i = Mi4 - 4.0 * im * Mi3 + 6.0 * im2 * Mi2 - 4.0 * im2 * im * Mi1 + im2 * im2 * M0;

        double c2o = Mo2 - 2.0 * om * Mo1 + om2 * M0;
        double c3o = Mo3 - 3.0 * om * Mo2 + 3.0 * om2 * Mo1 - om2 * om * M0;
        double c4o = Mo4 - 4.0 * om * Mo3 + 6.0 * om2 * Mo2 - 4.0 * om2 * om * Mo1 + om2 * om2 * M0;

        double iv = c2i / ms, ov = c2o / ms;
        double isk = c3i / (ms * (iv * sqrt(iv) + EPS));
        double osk = c3o / (ms * (ov * sqrt(ov) + EPS));
        double iku = c4i / (ms * (iv * iv + EPS));
        double oku = c4o / (ms * (ov * ov + EPS));

        double dm = im - om, dv = iv - ov, dsk = isk - osk, dku = iku - oku;
        double inten = dm * dm + dv * dv + dsk * dsk + dku * dku;
        double tex = sacc[9]  / NTOT;
        double shp = sacc[10] / NTOT;
        double total = inten + tex + 0.5 * shp;

        final_out[0] = (float)inten;
        final_out[1] = (float)tex;
        final_out[2] = (float)shp;
        final_out[3] = (float)total;
    }
}

extern "C" void kernel_launch(void* const* d_in, const int* in_sizes, int n_in,
                              void* d_out, int out_size) {
    const float* in_img  = (const float*)d_in[0];
    const float* out_img = (const float*)d_in[1];
    const float* mask    = (const float*)d_in[2];

    k_main<<<NBLK, NTHR>>>(in_img, out_img, mask, (float*)d_out);
}